// round 2
// baseline (speedup 1.0000x reference)
#include <cuda_runtime.h>

// Problem constants
#define BB 32
#define TT 128
#define EE 256
#define HH 1024
#define VV 32000
#define ZN 4096   // 4*H

// ---------------- device scratch (static, allocation-free) ----------------
__device__ float g_x[BB * TT * EE];     // embedded inputs  [b*T+t][e]   4 MB
__device__ float g_h1[BB * HH];
__device__ float g_c1[BB * HH];
__device__ float g_h2[BB * HH];
__device__ float g_c2[BB * HH];
__device__ float g_z[BB * ZN];          // gate pre-activations for current step/layer
__device__ float g_hs[BB * TT * HH];    // h2 history, row = b*T+t       16 MB

// ---------------- f32x2 packed-FMA helpers (sm_100+) ----------------
__device__ __forceinline__ unsigned long long pack2(float x, float y) {
    unsigned long long r;
    asm("mov.b64 %0, {%1, %2};" : "=l"(r) : "f"(x), "f"(y));
    return r;
}
__device__ __forceinline__ unsigned long long fma2(unsigned long long a,
                                                   unsigned long long b,
                                                   unsigned long long c) {
    unsigned long long d;
    asm("fma.rn.f32x2 %0, %1, %2, %3;" : "=l"(d) : "l"(a), "l"(b), "l"(c));
    return d;
}
__device__ __forceinline__ float2 unpack2(unsigned long long v) {
    float2 r;
    asm("mov.b64 {%0, %1}, %2;" : "=f"(r.x), "=f"(r.y) : "l"(v));
    return r;
}

// ---------------- embedding gather ----------------
// grid: BB*TT*EE/4/256 = 1024 blocks x 256 threads, float4 copies
__global__ void embed_kernel(const int* __restrict__ ids,
                             const float* __restrict__ emb) {
    int i  = blockIdx.x * blockDim.x + threadIdx.x;   // over BB*TT*(EE/4)
    int bt = i >> 6;                                  // EE/4 = 64
    int e4 = i & 63;
    int id = ids[bt];
    reinterpret_cast<float4*>(g_x)[(size_t)bt * 64 + e4] =
        reinterpret_cast<const float4*>(emb)[(size_t)id * 64 + e4];
}

// ---------------- zero LSTM state ----------------
__global__ void zero_state_kernel() {
    int i = blockIdx.x * blockDim.x + threadIdx.x;    // BB*HH = 32768
    g_h1[i] = 0.f; g_c1[i] = 0.f; g_h2[i] = 0.f; g_c2[i] = 0.f;
}

// ---------------- per-step gate GEMM: g_z[32][4096] = A @ W + bias ----------------
// A[32][K] is the concatenation of two regions:
//   LAYER 1: A0 = x_t (rows stride T*E, K0=E),  A1 = h1 (stride H)
//   LAYER 2: A0 = h1  (stride H,      K0=H),    A1 = h2 (stride H)
// Tiling: BM=32 (all batches), BN=32, BK=32; 128 blocks x 256 threads.
// Thread tile: 4 batches x 1 column.
template <int LAYER>
__global__ void gemm_z_kernel(int t,
                              const float* __restrict__ W,
                              const float* __restrict__ bias) {
    constexpr int K  = (LAYER == 1) ? (EE + HH) : (2 * HH);
    constexpr int K0 = (LAYER == 1) ? EE : HH;
    const float* A0  = (LAYER == 1) ? (g_x + (size_t)t * EE) : g_h1;
    const int lda0   = (LAYER == 1) ? (TT * EE) : HH;
    const float* A1  = (LAYER == 1) ? g_h1 : g_h2;

    __shared__ __align__(16) float a_s[32][36];   // [k][b], padded
    __shared__ float w_s[32][32];                  // [k][n]

    const int tid = threadIdx.x;
    const int n0  = blockIdx.x * 32;
    const int n   = tid & 31;
    const int bq  = tid >> 5;          // 0..7  (batch quad)
    const int sb  = tid >> 3;          // 0..31 (staging: batch row)
    const int skq = tid & 7;           // 0..7  (staging: k quad)
    const int wn  = tid & 31;          // staging: W column
    const int wkq = tid >> 5;          // 0..7

    float acc0 = 0.f, acc1 = 0.f, acc2 = 0.f, acc3 = 0.f;

    for (int kc = 0; kc < K; kc += 32) {
        // stage A chunk [32k x 32b], transposed into smem
        {
            int kg = kc + skq * 4;
            float4 av;
            if (kg < K0)
                av = *reinterpret_cast<const float4*>(A0 + (size_t)sb * lda0 + kg);
            else
                av = *reinterpret_cast<const float4*>(A1 + (size_t)sb * HH + (kg - K0));
            a_s[skq * 4 + 0][sb] = av.x;
            a_s[skq * 4 + 1][sb] = av.y;
            a_s[skq * 4 + 2][sb] = av.z;
            a_s[skq * 4 + 3][sb] = av.w;
        }
        // stage W chunk [32k x 32n]
        #pragma unroll
        for (int j = 0; j < 4; j++) {
            w_s[wkq * 4 + j][wn] = W[(size_t)(kc + wkq * 4 + j) * ZN + n0 + wn];
        }
        __syncthreads();
        #pragma unroll
        for (int k = 0; k < 32; k++) {
            float4 a = *reinterpret_cast<const float4*>(&a_s[k][bq << 2]);  // broadcast
            float  w = w_s[k][n];
            acc0 += a.x * w;
            acc1 += a.y * w;
            acc2 += a.z * w;
            acc3 += a.w * w;
        }
        __syncthreads();
    }

    float bv = bias[n0 + n];
    g_z[(size_t)(bq * 4 + 0) * ZN + n0 + n] = acc0 + bv;
    g_z[(size_t)(bq * 4 + 1) * ZN + n0 + n] = acc1 + bv;
    g_z[(size_t)(bq * 4 + 2) * ZN + n0 + n] = acc2 + bv;
    g_z[(size_t)(bq * 4 + 3) * ZN + n0 + n] = acc3 + bv;
}

// ---------------- LSTM gate nonlinearity (gate order i, j, f, o) ----------------
template <int LAYER>
__global__ void gates_kernel(int t) {
    int i = blockIdx.x * blockDim.x + threadIdx.x;  // BB*HH
    int b = i >> 10;
    int n = i & 1023;

    float* c = (LAYER == 1) ? g_c1 : g_c2;
    float* h = (LAYER == 1) ? g_h1 : g_h2;

    const float* zr = g_z + (size_t)b * ZN;
    float zi = zr[n];
    float zj = zr[HH + n];
    float zf = zr[2 * HH + n];
    float zo = zr[3 * HH + n];

    float si = 1.f / (1.f + expf(-zi));
    float sf = 1.f / (1.f + expf(-zf));
    float so = 1.f / (1.f + expf(-zo));

    float cn = c[i] * sf + si * tanhf(zj);
    float hn = tanhf(cn) * so;

    c[i] = cn;
    h[i] = hn;
    if (LAYER == 2) {
        g_hs[((size_t)b * TT + t) * HH + n] = hn;   // output row = b*T + t
    }
}

// ---------------- final logits GEMM: out[4096][32000] = hs @ Wv^T + sb ----------------
// BM=64, BN=64, BK=16, 256 threads, 4x4 micro-tile, f32x2 packed FMA.
__global__ void logits_kernel(const float* __restrict__ Wv,     // [V][H]
                              const float* __restrict__ sbias,  // [V]
                              float* __restrict__ out) {
    __shared__ __align__(16) float a_s[16][64];   // [k][m]
    __shared__ __align__(16) float w_s[16][64];   // [k][v]

    const int tid  = threadIdx.x;
    const int m0   = blockIdx.y * 64;
    const int v0   = blockIdx.x * 64;
    const int ty   = tid >> 4;         // 0..15 -> 4 m rows
    const int tx   = tid & 15;         // 0..15 -> 4 v cols
    const int srow = tid >> 2;         // 0..63 staging row
    const int skq  = (tid & 3) * 4;    // staging k offset

    unsigned long long acc[4][2];
    #pragma unroll
    for (int i = 0; i < 4; i++) { acc[i][0] = 0ULL; acc[i][1] = 0ULL; }

    const float* Arow = g_hs + (size_t)(m0 + srow) * HH + skq;
    const float* Wrow = Wv   + (size_t)(v0 + srow) * HH + skq;

    for (int k0 = 0; k0 < HH; k0 += 16) {
        float4 av = *reinterpret_cast<const float4*>(Arow + k0);
        float4 wv = *reinterpret_cast<const float4*>(Wrow + k0);
        a_s[skq + 0][srow] = av.x; a_s[skq + 1][srow] = av.y;
        a_s[skq + 2][srow] = av.z; a_s[skq + 3][srow] = av.w;
        w_s[skq + 0][srow] = wv.x; w_s[skq + 1][srow] = wv.y;
        w_s[skq + 2][srow] = wv.z; w_s[skq + 3][srow] = wv.w;
        __syncthreads();
        #pragma unroll
        for (int k = 0; k < 16; k++) {
            float4 a = *reinterpret_cast<const float4*>(&a_s[k][ty << 2]);
            unsigned long long w01 =
                *reinterpret_cast<const unsigned long long*>(&w_s[k][tx << 2]);
            unsigned long long w23 =
                *reinterpret_cast<const unsigned long long*>(&w_s[k][(tx << 2) + 2]);
            unsigned long long ax = pack2(a.x, a.x);
            unsigned long long ay = pack2(a.y, a.y);
            unsigned long long az = pack2(a.z, a.z);
            unsigned long long aw = pack2(a.w, a.w);
            acc[0][0] = fma2(ax, w01, acc[0][0]); acc[0][1] = fma2(ax, w23, acc[0][1]);
            acc[1][0] = fma2(ay, w01, acc[1][0]); acc[1][1] = fma2(ay, w23, acc[1][1]);
            acc[2][0] = fma2(az, w01, acc[2][0]); acc[2][1] = fma2(az, w23, acc[2][1]);
            acc[3][0] = fma2(aw, w01, acc[3][0]); acc[3][1] = fma2(aw, w23, acc[3][1]);
        }
        __syncthreads();
    }

    const int col = v0 + (tx << 2);
    float4 sv = *reinterpret_cast<const float4*>(sbias + col);
    #pragma unroll
    for (int i = 0; i < 4; i++) {
        float2 r0 = unpack2(acc[i][0]);
        float2 r1 = unpack2(acc[i][1]);
        float4 o;
        o.x = r0.x + sv.x; o.y = r0.y + sv.y;
        o.z = r1.x + sv.z; o.w = r1.y + sv.w;
        *reinterpret_cast<float4*>(out + (size_t)(m0 + (ty << 2) + i) * VV + col) = o;
    }
}

// ---------------- launch ----------------
extern "C" void kernel_launch(void* const* d_in, const int* in_sizes, int n_in,
                              void* d_out, int out_size) {
    const int*   ids = (const int*)d_in[0];     // input_data [B,T] int32
    const float* emb = (const float*)d_in[1];   // [VOCAB,E]
    const float* W1  = (const float*)d_in[2];   // [E+H, 4H]
    const float* b1  = (const float*)d_in[3];   // [4H]
    const float* W2  = (const float*)d_in[4];   // [H+H, 4H]
    const float* b2  = (const float*)d_in[5];   // [4H]
    const float* Wv  = (const float*)d_in[6];   // [VOCAB, H]
    const float* sb  = (const float*)d_in[7];   // [VOCAB]
    float* out = (float*)d_out;                 // [B*T, VOCAB]

    embed_kernel<<<(BB * TT * (EE / 4)) / 256, 256>>>(ids, emb);
    zero_state_kernel<<<(BB * HH) / 256, 256>>>();

    for (int t = 0; t < TT; t++) {
        gemm_z_kernel<1><<<ZN / 32, 256>>>(t, W1, b1);
        gates_kernel<1><<<(BB * HH) / 256, 256>>>(t);
        gemm_z_kernel<2><<<ZN / 32, 256>>>(t, W2, b2);
        gates_kernel<2><<<(BB * HH) / 256, 256>>>(t);
    }

    dim3 grid(VV / 64, (BB * TT) / 64);
    logits_kernel<<<grid, 256>>>(Wv, sb, out);
}

// round 3
// speedup vs baseline: 1.8332x; 1.8332x over previous
#include <cuda_runtime.h>

#define BB 32
#define TT 128
#define EE 256
#define HH 1024
#define VV 32000
#define ZN 4096          // 4*H
#define NBLK 148         // persistent grid size (<= SM count, co-resident)

typedef unsigned long long ull;

// ---------------- device scratch (static, allocation-free) ----------------
__device__ __align__(16) float g_zx[(size_t)TT * BB * ZN];   // x@W1x + b1, row = t*32+b  (64 MB)
__device__ __align__(16) float g_h1[BB * HH];
__device__ __align__(16) float g_c1[BB * HH];
__device__ __align__(16) float g_h2[BB * HH];
__device__ __align__(16) float g_c2[BB * HH];
__device__ __align__(16) float g_z1p[4 * BB * ZN];           // layer1 K-split partials (2 MB)
__device__ __align__(16) float g_z2p[8 * BB * ZN];           // layer2 K-split partials (4 MB)
__device__ __align__(16) float g_hs[(size_t)BB * TT * HH];   // h2 history, row = b*T+t (16 MB)

__device__ unsigned int g_arrive;
__device__ unsigned int g_gen;

// ---------------- f32x2 helpers ----------------
__device__ __forceinline__ ull pack2(float x, float y) {
    ull r;
    asm("mov.b64 %0, {%1, %2};" : "=l"(r) : "f"(x), "f"(y));
    return r;
}
__device__ __forceinline__ ull fma2(ull a, ull b, ull c) {
    ull d;
    asm("fma.rn.f32x2 %0, %1, %2, %3;" : "=l"(d) : "l"(a), "l"(b), "l"(c));
    return d;
}
__device__ __forceinline__ float2 unpack2(ull v) {
    float2 r;
    asm("mov.b64 {%0, %1}, %2;" : "=f"(r.x), "=f"(r.y) : "l"(v));
    return r;
}

// ---------------- grid-wide barrier (persistent kernel, all blocks resident) ----------------
__device__ __forceinline__ void grid_bar(unsigned int target) {
    __syncthreads();
    if (threadIdx.x == 0) {
        __threadfence();
        unsigned int old = atomicAdd(&g_arrive, 1u);
        if (old == gridDim.x - 1) {
            atomicExch(&g_arrive, 0u);
            asm volatile("st.release.gpu.u32 [%0], %1;" :: "l"(&g_gen), "r"(target) : "memory");
        } else {
            unsigned int cur;
            do {
                asm volatile("ld.acquire.gpu.u32 %0, [%1];" : "=r"(cur) : "l"(&g_gen) : "memory");
            } while (cur < target);
        }
    }
    __syncthreads();
}

// ============================================================================
// zx precompute: g_zx[t*32+b][n] = b1[n] + emb[ids[b][t]] @ W1[0:256]
// BM=64, BN=64, BK=16, 256 threads, 4x4 micro-tile (f32x2). Also resets barrier state.
// ============================================================================
__global__ void __launch_bounds__(256) zx_kernel(const int* __restrict__ ids,
                                                 const float* __restrict__ emb,
                                                 const float* __restrict__ W1,
                                                 const float* __restrict__ b1) {
    if (blockIdx.x == 0 && blockIdx.y == 0 && threadIdx.x == 0) {
        g_arrive = 0u;
        g_gen = 0u;
    }
    __shared__ __align__(16) float a_s[16 * 68];   // [k][m], pad 68
    __shared__ __align__(16) float w_s[16 * 68];   // [k][n], pad 68

    const int tid  = threadIdx.x;
    const int m0   = blockIdx.y * 64;
    const int n0   = blockIdx.x * 64;
    const int srow = tid >> 2;
    const int skq  = (tid & 3) * 4;
    const int wk   = tid >> 4;
    const int wn   = (tid & 15) * 4;
    const int ty   = tid >> 4;
    const int tx   = tid & 15;

    const int r  = m0 + srow;
    const int bb = r & 31;
    const int tt = r >> 5;
    const float* arow = emb + (size_t)ids[bb * TT + tt] * EE + skq;

    ull acc[4][2];
    #pragma unroll
    for (int i = 0; i < 4; i++) { acc[i][0] = 0ULL; acc[i][1] = 0ULL; }

    for (int k0 = 0; k0 < EE; k0 += 16) {
        float4 av = *reinterpret_cast<const float4*>(arow + k0);
        a_s[(skq + 0) * 68 + srow] = av.x;
        a_s[(skq + 1) * 68 + srow] = av.y;
        a_s[(skq + 2) * 68 + srow] = av.z;
        a_s[(skq + 3) * 68 + srow] = av.w;
        *reinterpret_cast<float4*>(w_s + wk * 68 + wn) =
            *reinterpret_cast<const float4*>(W1 + (size_t)(k0 + wk) * ZN + n0 + wn);
        __syncthreads();
        #pragma unroll
        for (int k = 0; k < 16; k++) {
            float4 a = *reinterpret_cast<const float4*>(a_s + k * 68 + ty * 4);
            ulonglong2 w = *reinterpret_cast<const ulonglong2*>(w_s + k * 68 + tx * 4);
            ull ax = pack2(a.x, a.x), ay = pack2(a.y, a.y);
            ull az = pack2(a.z, a.z), aw = pack2(a.w, a.w);
            acc[0][0] = fma2(ax, w.x, acc[0][0]); acc[0][1] = fma2(ax, w.y, acc[0][1]);
            acc[1][0] = fma2(ay, w.x, acc[1][0]); acc[1][1] = fma2(ay, w.y, acc[1][1]);
            acc[2][0] = fma2(az, w.x, acc[2][0]); acc[2][1] = fma2(az, w.y, acc[2][1]);
            acc[3][0] = fma2(aw, w.x, acc[3][0]); acc[3][1] = fma2(aw, w.y, acc[3][1]);
        }
        __syncthreads();
    }

    float4 bv = *reinterpret_cast<const float4*>(b1 + n0 + tx * 4);
    #pragma unroll
    for (int i = 0; i < 4; i++) {
        float2 r0 = unpack2(acc[i][0]);
        float2 r1 = unpack2(acc[i][1]);
        float4 o;
        o.x = r0.x + bv.x; o.y = r0.y + bv.y;
        o.z = r1.x + bv.z; o.w = r1.y + bv.w;
        *reinterpret_cast<float4*>(g_zx + (size_t)(m0 + ty * 4 + i) * ZN + n0 + tx * 4) = o;
    }
}

// ============================================================================
// Persistent LSTM kernel
// ============================================================================

// One K-chunk GEMM task: pout[32][n0:n0+128] = hsrc[32][0:256] @ wrow[0:256][n0:n0+128]
// hsrc row stride HH; wrow row stride ZN. BK=32, 256 threads, 4b x 4n micro (f32x2).
__device__ __forceinline__ void gemm_task(const float* __restrict__ hsrc,
                                          const float* __restrict__ wrow,
                                          float* __restrict__ pout, int n0,
                                          float* a_s /*32x36*/, float* w_s /*32x128*/) {
    const int tid = threadIdx.x;
    const int sb  = tid >> 3;
    const int skq = (tid & 7) << 2;
    const int tx  = tid & 31;
    const int bq  = tid >> 5;
    const float* ap = hsrc + (size_t)sb * HH + skq;

    ull acc[4][2];
    #pragma unroll
    for (int i = 0; i < 4; i++) { acc[i][0] = 0ULL; acc[i][1] = 0ULL; }

    float4 pa = *reinterpret_cast<const float4*>(ap);
    float4 pw[4];
    #pragma unroll
    for (int j = 0; j < 4; j++) {
        int idx = tid + j * 256, row = idx >> 5, c4 = (idx & 31) << 2;
        pw[j] = *reinterpret_cast<const float4*>(wrow + (size_t)row * ZN + n0 + c4);
    }

    for (int kt = 0; kt < 256; kt += 32) {
        a_s[(skq + 0) * 36 + sb] = pa.x;
        a_s[(skq + 1) * 36 + sb] = pa.y;
        a_s[(skq + 2) * 36 + sb] = pa.z;
        a_s[(skq + 3) * 36 + sb] = pa.w;
        #pragma unroll
        for (int j = 0; j < 4; j++) {
            int idx = tid + j * 256, row = idx >> 5, c4 = (idx & 31) << 2;
            *reinterpret_cast<float4*>(w_s + row * 128 + c4) = pw[j];
        }
        __syncthreads();
        if (kt + 32 < 256) {
            pa = *reinterpret_cast<const float4*>(ap + kt + 32);
            #pragma unroll
            for (int j = 0; j < 4; j++) {
                int idx = tid + j * 256, row = idx >> 5, c4 = (idx & 31) << 2;
                pw[j] = *reinterpret_cast<const float4*>(wrow + (size_t)(kt + 32 + row) * ZN + n0 + c4);
            }
        }
        #pragma unroll
        for (int k = 0; k < 32; k++) {
            float4 a = *reinterpret_cast<const float4*>(a_s + k * 36 + (bq << 2));
            ulonglong2 w = *reinterpret_cast<const ulonglong2*>(w_s + k * 128 + (tx << 2));
            ull ax = pack2(a.x, a.x), ay = pack2(a.y, a.y);
            ull az = pack2(a.z, a.z), aw = pack2(a.w, a.w);
            acc[0][0] = fma2(ax, w.x, acc[0][0]); acc[0][1] = fma2(ax, w.y, acc[0][1]);
            acc[1][0] = fma2(ay, w.x, acc[1][0]); acc[1][1] = fma2(ay, w.y, acc[1][1]);
            acc[2][0] = fma2(az, w.x, acc[2][0]); acc[2][1] = fma2(az, w.y, acc[2][1]);
            acc[3][0] = fma2(aw, w.x, acc[3][0]); acc[3][1] = fma2(aw, w.y, acc[3][1]);
        }
        __syncthreads();
    }

    #pragma unroll
    for (int i = 0; i < 4; i++) {
        float2 r0 = unpack2(acc[i][0]);
        float2 r1 = unpack2(acc[i][1]);
        float4 o; o.x = r0.x; o.y = r0.y; o.z = r1.x; o.w = r1.y;
        *reinterpret_cast<float4*>(pout + (size_t)((bq << 2) + i) * ZN + n0 + (tx << 2)) = o;
    }
}

__device__ __forceinline__ float sigf(float x) { return 1.f / (1.f + expf(-x)); }

__device__ __forceinline__ void gates1_work(int t) {
    int idx = blockIdx.x * 256 + threadIdx.x;
    if (idx >= BB * HH) return;
    int b = idx >> 10, n = idx & (HH - 1);
    const float* zx = g_zx + ((size_t)t * BB + b) * ZN;
    float zi = zx[n], zj = zx[HH + n], zf = zx[2 * HH + n], zo = zx[3 * HH + n];
    #pragma unroll
    for (int kc = 0; kc < 4; kc++) {
        const float* p = g_z1p + ((size_t)kc * BB + b) * ZN;
        zi += p[n]; zj += p[HH + n]; zf += p[2 * HH + n]; zo += p[3 * HH + n];
    }
    float cn = g_c1[idx] * sigf(zf) + sigf(zi) * tanhf(zj);
    g_c1[idx] = cn;
    g_h1[idx] = tanhf(cn) * sigf(zo);
}

__device__ __forceinline__ void gates2_work(int t, const float* __restrict__ b2) {
    int idx = blockIdx.x * 256 + threadIdx.x;
    if (idx >= BB * HH) return;
    int b = idx >> 10, n = idx & (HH - 1);
    float zi = b2[n], zj = b2[HH + n], zf = b2[2 * HH + n], zo = b2[3 * HH + n];
    #pragma unroll
    for (int kc = 0; kc < 8; kc++) {
        const float* p = g_z2p + ((size_t)kc * BB + b) * ZN;
        zi += p[n]; zj += p[HH + n]; zf += p[2 * HH + n]; zo += p[3 * HH + n];
    }
    float cn = g_c2[idx] * sigf(zf) + sigf(zi) * tanhf(zj);
    g_c2[idx] = cn;
    float hn = tanhf(cn) * sigf(zo);
    g_h2[idx] = hn;
    g_hs[((size_t)b * TT + t) * HH + n] = hn;
}

__global__ void __launch_bounds__(256) lstm_kernel(const float* __restrict__ W1,
                                                   const float* __restrict__ W2,
                                                   const float* __restrict__ b2) {
    __shared__ __align__(16) float a_s[32 * 36];
    __shared__ __align__(16) float w_s[32 * 128];
    unsigned int bar = 0;
    const int bid = blockIdx.x, tid = threadIdx.x;

    for (int i = bid * 256 + tid; i < BB * HH; i += NBLK * 256) {
        g_h1[i] = 0.f; g_c1[i] = 0.f; g_h2[i] = 0.f; g_c2[i] = 0.f;
    }
    grid_bar(++bar);

    for (int t = 0; t < TT; t++) {
        // phase [gates2(t-1) + layer1 GEMM(t)]
        if (t > 0) gates2_work(t - 1, b2);
        if (bid < 128) {
            int ntile = bid & 31, kc = bid >> 5;
            gemm_task(g_h1 + kc * 256,
                      W1 + (size_t)(EE + kc * 256) * ZN,
                      g_z1p + (size_t)kc * BB * ZN,
                      ntile * 128, a_s, w_s);
        }
        grid_bar(++bar);

        gates1_work(t);
        grid_bar(++bar);

        // layer2 GEMM: 256 tasks over 148 blocks
        #pragma unroll
        for (int rep = 0; rep < 2; rep++) {
            int tk = bid + rep * NBLK;
            if (tk < 256) {
                int ntile = tk & 31, kc = tk >> 5;
                const float* hsrc = (kc < 4 ? g_h1 : g_h2) + (kc & 3) * 256;
                gemm_task(hsrc,
                          W2 + (size_t)kc * 256 * ZN,
                          g_z2p + (size_t)kc * BB * ZN,
                          ntile * 128, a_s, w_s);
            }
        }
        grid_bar(++bar);
    }
    gates2_work(TT - 1, b2);
}

// ============================================================================
// logits: out[4096][32000] = g_hs @ Wv^T + sb
// BM=BN=128, BK=16, 256 threads, 8x8 micro-tile (f32x2), reg prefetch.
// ============================================================================
__global__ void __launch_bounds__(256) logits_kernel(const float* __restrict__ Wv,
                                                     const float* __restrict__ sbias,
                                                     float* __restrict__ out) {
    __shared__ __align__(16) float a_s[16 * 132];
    __shared__ __align__(16) float w_s[16 * 132];

    const int tid  = threadIdx.x;
    const int m0   = blockIdx.y * 128;
    const int v0   = blockIdx.x * 128;
    const int srow = tid >> 1;
    const int sk   = (tid & 1) * 8;
    const int ty   = tid >> 4;
    const int tx   = tid & 15;

    const float* arow = g_hs + (size_t)(m0 + srow) * HH + sk;
    const float* wrow = Wv   + (size_t)(v0 + srow) * HH + sk;

    ull acc[8][4];
    #pragma unroll
    for (int i = 0; i < 8; i++)
        #pragma unroll
        for (int j = 0; j < 4; j++) acc[i][j] = 0ULL;

    float4 pa0 = *reinterpret_cast<const float4*>(arow);
    float4 pa1 = *reinterpret_cast<const float4*>(arow + 4);
    float4 pw0 = *reinterpret_cast<const float4*>(wrow);
    float4 pw1 = *reinterpret_cast<const float4*>(wrow + 4);

    for (int k0 = 0; k0 < HH; k0 += 16) {
        a_s[(sk + 0) * 132 + srow] = pa0.x; a_s[(sk + 1) * 132 + srow] = pa0.y;
        a_s[(sk + 2) * 132 + srow] = pa0.z; a_s[(sk + 3) * 132 + srow] = pa0.w;
        a_s[(sk + 4) * 132 + srow] = pa1.x; a_s[(sk + 5) * 132 + srow] = pa1.y;
        a_s[(sk + 6) * 132 + srow] = pa1.z; a_s[(sk + 7) * 132 + srow] = pa1.w;
        w_s[(sk + 0) * 132 + srow] = pw0.x; w_s[(sk + 1) * 132 + srow] = pw0.y;
        w_s[(sk + 2) * 132 + srow] = pw0.z; w_s[(sk + 3) * 132 + srow] = pw0.w;
        w_s[(sk + 4) * 132 + srow] = pw1.x; w_s[(sk + 5) * 132 + srow] = pw1.y;
        w_s[(sk + 6) * 132 + srow] = pw1.z; w_s[(sk + 7) * 132 + srow] = pw1.w;
        __syncthreads();
        if (k0 + 16 < HH) {
            pa0 = *reinterpret_cast<const float4*>(arow + k0 + 16);
            pa1 = *reinterpret_cast<const float4*>(arow + k0 + 20);
            pw0 = *reinterpret_cast<const float4*>(wrow + k0 + 16);
            pw1 = *reinterpret_cast<const float4*>(wrow + k0 + 20);
        }
        #pragma unroll
        for (int k = 0; k < 16; k++) {
            const float* ab = a_s + k * 132 + ty * 8;
            float4 a0 = *reinterpret_cast<const float4*>(ab);
            float4 a1 = *reinterpret_cast<const float4*>(ab + 4);
            ulonglong2 w0 = *reinterpret_cast<const ulonglong2*>(w_s + k * 132 + tx * 8);
            ulonglong2 w1 = *reinterpret_cast<const ulonglong2*>(w_s + k * 132 + tx * 8 + 4);
            ull s;
            s = pack2(a0.x, a0.x);
            acc[0][0] = fma2(s, w0.x, acc[0][0]); acc[0][1] = fma2(s, w0.y, acc[0][1]);
            acc[0][2] = fma2(s, w1.x, acc[0][2]); acc[0][3] = fma2(s, w1.y, acc[0][3]);
            s = pack2(a0.y, a0.y);
            acc[1][0] = fma2(s, w0.x, acc[1][0]); acc[1][1] = fma2(s, w0.y, acc[1][1]);
            acc[1][2] = fma2(s, w1.x, acc[1][2]); acc[1][3] = fma2(s, w1.y, acc[1][3]);
            s = pack2(a0.z, a0.z);
            acc[2][0] = fma2(s, w0.x, acc[2][0]); acc[2][1] = fma2(s, w0.y, acc[2][1]);
            acc[2][2] = fma2(s, w1.x, acc[2][2]); acc[2][3] = fma2(s, w1.y, acc[2][3]);
            s = pack2(a0.w, a0.w);
            acc[3][0] = fma2(s, w0.x, acc[3][0]); acc[3][1] = fma2(s, w0.y, acc[3][1]);
            acc[3][2] = fma2(s, w1.x, acc[3][2]); acc[3][3] = fma2(s, w1.y, acc[3][3]);
            s = pack2(a1.x, a1.x);
            acc[4][0] = fma2(s, w0.x, acc[4][0]); acc[4][1] = fma2(s, w0.y, acc[4][1]);
            acc[4][2] = fma2(s, w1.x, acc[4][2]); acc[4][3] = fma2(s, w1.y, acc[4][3]);
            s = pack2(a1.y, a1.y);
            acc[5][0] = fma2(s, w0.x, acc[5][0]); acc[5][1] = fma2(s, w0.y, acc[5][1]);
            acc[5][2] = fma2(s, w1.x, acc[5][2]); acc[5][3] = fma2(s, w1.y, acc[5][3]);
            s = pack2(a1.z, a1.z);
            acc[6][0] = fma2(s, w0.x, acc[6][0]); acc[6][1] = fma2(s, w0.y, acc[6][1]);
            acc[6][2] = fma2(s, w1.x, acc[6][2]); acc[6][3] = fma2(s, w1.y, acc[6][3]);
            s = pack2(a1.w, a1.w);
            acc[7][0] = fma2(s, w0.x, acc[7][0]); acc[7][1] = fma2(s, w0.y, acc[7][1]);
            acc[7][2] = fma2(s, w1.x, acc[7][2]); acc[7][3] = fma2(s, w1.y, acc[7][3]);
        }
        __syncthreads();
    }

    float4 sb0 = *reinterpret_cast<const float4*>(sbias + v0 + tx * 8);
    float4 sb1 = *reinterpret_cast<const float4*>(sbias + v0 + tx * 8 + 4);
    #pragma unroll
    for (int i = 0; i < 8; i++) {
        float2 r0 = unpack2(acc[i][0]);
        float2 r1 = unpack2(acc[i][1]);
        float2 r2 = unpack2(acc[i][2]);
        float2 r3 = unpack2(acc[i][3]);
        float4 o0, o1;
        o0.x = r0.x + sb0.x; o0.y = r0.y + sb0.y; o0.z = r1.x + sb0.z; o0.w = r1.y + sb0.w;
        o1.x = r2.x + sb1.x; o1.y = r2.y + sb1.y; o1.z = r3.x + sb1.z; o1.w = r3.y + sb1.w;
        float* orow = out + (size_t)(m0 + ty * 8 + i) * VV + v0 + tx * 8;
        *reinterpret_cast<float4*>(orow)     = o0;
        *reinterpret_cast<float4*>(orow + 4) = o1;
    }
}

// ---------------- launch ----------------
extern "C" void kernel_launch(void* const* d_in, const int* in_sizes, int n_in,
                              void* d_out, int out_size) {
    const int*   ids = (const int*)d_in[0];     // [B,T] int32
    const float* emb = (const float*)d_in[1];   // [VOCAB,E]
    const float* W1  = (const float*)d_in[2];   // [E+H, 4H]
    const float* b1  = (const float*)d_in[3];   // [4H]
    const float* W2  = (const float*)d_in[4];   // [2H, 4H]
    const float* b2  = (const float*)d_in[5];   // [4H]
    const float* Wv  = (const float*)d_in[6];   // [VOCAB, H]
    const float* sb  = (const float*)d_in[7];   // [VOCAB]
    float* out = (float*)d_out;                 // [B*T, VOCAB]

    dim3 zxg(ZN / 64, (TT * BB) / 64);
    zx_kernel<<<zxg, 256>>>(ids, emb, W1, b1);

    lstm_kernel<<<NBLK, 256>>>(W1, W2, b2);

    dim3 lg(VV / 128, (BB * TT) / 128);
    logits_kernel<<<lg, 256>>>(Wv, sb, out);
}

// round 5
// speedup vs baseline: 2.8502x; 1.5548x over previous
#include <cuda_runtime.h>
#include <cuda_bf16.h>
#include <cstdint>

#define BB 32
#define TT 128
#define EE 256
#define HH 1024
#define VV 32000
#define ZN 4096          // 4*H
#define NBLK 148         // persistent grid size (<= SM count, co-resident)

typedef unsigned long long ull;

// ---------------- device scratch (static, allocation-free) ----------------
__device__ __align__(16) float g_zx[(size_t)TT * BB * ZN];   // x@W1x + b1, row = t*32+b
__device__ __align__(16) float g_h1[BB * HH];
__device__ __align__(16) float g_c1[BB * HH];
__device__ __align__(16) float g_h2[BB * HH];
__device__ __align__(16) float g_c2[BB * HH];
__device__ __align__(16) float g_z1p[4 * BB * ZN];           // layer1 K-split partials
__device__ __align__(16) float g_z2p[8 * BB * ZN];           // layer2 K-split partials
__device__ __align__(16) float g_hs[(size_t)BB * TT * HH];   // h2 history, row = b*T+t

// bf16 hi/lo split operands for the tensor-core logits GEMM
__device__ __align__(16) __nv_bfloat16 g_Ahi[(size_t)BB * TT * HH];
__device__ __align__(16) __nv_bfloat16 g_Alo[(size_t)BB * TT * HH];
__device__ __align__(16) __nv_bfloat16 g_Whi[(size_t)VV * HH];
__device__ __align__(16) __nv_bfloat16 g_Wlo[(size_t)VV * HH];

__device__ unsigned int g_arrive;
__device__ unsigned int g_gen;

// ---------------- f32x2 helpers ----------------
__device__ __forceinline__ ull pack2(float x, float y) {
    ull r;
    asm("mov.b64 %0, {%1, %2};" : "=l"(r) : "f"(x), "f"(y));
    return r;
}
__device__ __forceinline__ ull fma2(ull a, ull b, ull c) {
    ull d;
    asm("fma.rn.f32x2 %0, %1, %2, %3;" : "=l"(d) : "l"(a), "l"(b), "l"(c));
    return d;
}
__device__ __forceinline__ float2 unpack2(ull v) {
    float2 r;
    asm("mov.b64 {%0, %1}, %2;" : "=f"(r.x), "=f"(r.y) : "l"(v));
    return r;
}

// ---------------- base-ISA tensor helpers ----------------
__device__ __forceinline__ uint32_t smem_u32(const void* p) {
    uint32_t a;
    asm("{ .reg .u64 t; cvta.to.shared.u64 t, %1; cvt.u32.u64 %0, t; }" : "=r"(a) : "l"(p));
    return a;
}
#define SWZ128(off) ((off) ^ (((off) >> 3) & 0x70))
#define CP_ASYNC16(saddr, gaddr) \
    asm volatile("cp.async.cg.shared.global [%0], [%1], 16;" :: "r"(saddr), "l"(gaddr))
#define CP_COMMIT() asm volatile("cp.async.commit_group;" ::: "memory")
#define CP_WAIT0()  asm volatile("cp.async.wait_group 0;" ::: "memory")
#define LDSM_X4(r0, r1, r2, r3, addr) \
    asm volatile("ldmatrix.sync.aligned.m8n8.x4.shared.b16 {%0,%1,%2,%3}, [%4];" \
        : "=r"(r0), "=r"(r1), "=r"(r2), "=r"(r3) : "r"(addr))
#define MMA16816(d, a, b) \
    asm volatile("mma.sync.aligned.m16n8k16.row.col.f32.bf16.bf16.f32 " \
        "{%0,%1,%2,%3}, {%4,%5,%6,%7}, {%8,%9}, {%0,%1,%2,%3};" \
        : "+f"((d)[0]), "+f"((d)[1]), "+f"((d)[2]), "+f"((d)[3]) \
        : "r"((a)[0]), "r"((a)[1]), "r"((a)[2]), "r"((a)[3]), "r"((b)[0]), "r"((b)[1]))

// ---------------- grid-wide barrier (persistent kernel, all blocks resident) ----------------
__device__ __forceinline__ void grid_bar(unsigned int target) {
    __syncthreads();
    if (threadIdx.x == 0) {
        __threadfence();
        unsigned int old = atomicAdd(&g_arrive, 1u);
        if (old == gridDim.x - 1) {
            atomicExch(&g_arrive, 0u);
            asm volatile("st.release.gpu.u32 [%0], %1;" :: "l"(&g_gen), "r"(target) : "memory");
        } else {
            unsigned int cur;
            do {
                asm volatile("ld.acquire.gpu.u32 %0, [%1];" : "=r"(cur) : "l"(&g_gen) : "memory");
            } while (cur < target);
        }
    }
    __syncthreads();
}

// ============================================================================
// zx precompute: g_zx[t*32+b][n] = b1[n] + emb[ids[b][t]] @ W1[0:256]
// ============================================================================
__global__ void __launch_bounds__(256) zx_kernel(const int* __restrict__ ids,
                                                 const float* __restrict__ emb,
                                                 const float* __restrict__ W1,
                                                 const float* __restrict__ b1) {
    if (blockIdx.x == 0 && blockIdx.y == 0 && threadIdx.x == 0) {
        g_arrive = 0u;
        g_gen = 0u;
    }
    __shared__ __align__(16) float a_s[16 * 68];
    __shared__ __align__(16) float w_s[16 * 68];

    const int tid  = threadIdx.x;
    const int m0   = blockIdx.y * 64;
    const int n0   = blockIdx.x * 64;
    const int srow = tid >> 2;
    const int skq  = (tid & 3) * 4;
    const int wk   = tid >> 4;
    const int wn   = (tid & 15) * 4;
    const int ty   = tid >> 4;
    const int tx   = tid & 15;

    const int r  = m0 + srow;
    const int bb = r & 31;
    const int tt = r >> 5;
    const float* arow = emb + (size_t)ids[bb * TT + tt] * EE + skq;

    ull acc[4][2];
    #pragma unroll
    for (int i = 0; i < 4; i++) { acc[i][0] = 0ULL; acc[i][1] = 0ULL; }

    for (int k0 = 0; k0 < EE; k0 += 16) {
        float4 av = *reinterpret_cast<const float4*>(arow + k0);
        a_s[(skq + 0) * 68 + srow] = av.x;
        a_s[(skq + 1) * 68 + srow] = av.y;
        a_s[(skq + 2) * 68 + srow] = av.z;
        a_s[(skq + 3) * 68 + srow] = av.w;
        *reinterpret_cast<float4*>(w_s + wk * 68 + wn) =
            *reinterpret_cast<const float4*>(W1 + (size_t)(k0 + wk) * ZN + n0 + wn);
        __syncthreads();
        #pragma unroll
        for (int k = 0; k < 16; k++) {
            float4 a = *reinterpret_cast<const float4*>(a_s + k * 68 + ty * 4);
            ulonglong2 w = *reinterpret_cast<const ulonglong2*>(w_s + k * 68 + tx * 4);
            ull ax = pack2(a.x, a.x), ay = pack2(a.y, a.y);
            ull az = pack2(a.z, a.z), aw = pack2(a.w, a.w);
            acc[0][0] = fma2(ax, w.x, acc[0][0]); acc[0][1] = fma2(ax, w.y, acc[0][1]);
            acc[1][0] = fma2(ay, w.x, acc[1][0]); acc[1][1] = fma2(ay, w.y, acc[1][1]);
            acc[2][0] = fma2(az, w.x, acc[2][0]); acc[2][1] = fma2(az, w.y, acc[2][1]);
            acc[3][0] = fma2(aw, w.x, acc[3][0]); acc[3][1] = fma2(aw, w.y, acc[3][1]);
        }
        __syncthreads();
    }

    float4 bv = *reinterpret_cast<const float4*>(b1 + n0 + tx * 4);
    #pragma unroll
    for (int i = 0; i < 4; i++) {
        float2 r0 = unpack2(acc[i][0]);
        float2 r1 = unpack2(acc[i][1]);
        float4 o;
        o.x = r0.x + bv.x; o.y = r0.y + bv.y;
        o.z = r1.x + bv.z; o.w = r1.y + bv.w;
        *reinterpret_cast<float4*>(g_zx + (size_t)(m0 + ty * 4 + i) * ZN + n0 + tx * 4) = o;
    }
}

// ============================================================================
// Persistent LSTM kernel
// ============================================================================
__device__ __forceinline__ void gemm_task(const float* __restrict__ hsrc,
                                          const float* __restrict__ wrow,
                                          float* __restrict__ pout, int n0,
                                          float* a_s /*32x36*/, float* w_s /*32x128*/) {
    const int tid = threadIdx.x;
    const int sb  = tid >> 3;
    const int skq = (tid & 7) << 2;
    const int tx  = tid & 31;
    const int bq  = tid >> 5;
    const float* ap = hsrc + (size_t)sb * HH + skq;

    ull acc[4][2];
    #pragma unroll
    for (int i = 0; i < 4; i++) { acc[i][0] = 0ULL; acc[i][1] = 0ULL; }

    float4 pa = *reinterpret_cast<const float4*>(ap);
    float4 pw[4];
    #pragma unroll
    for (int j = 0; j < 4; j++) {
        int idx = tid + j * 256, row = idx >> 5, c4 = (idx & 31) << 2;
        pw[j] = *reinterpret_cast<const float4*>(wrow + (size_t)row * ZN + n0 + c4);
    }

    for (int kt = 0; kt < 256; kt += 32) {
        a_s[(skq + 0) * 36 + sb] = pa.x;
        a_s[(skq + 1) * 36 + sb] = pa.y;
        a_s[(skq + 2) * 36 + sb] = pa.z;
        a_s[(skq + 3) * 36 + sb] = pa.w;
        #pragma unroll
        for (int j = 0; j < 4; j++) {
            int idx = tid + j * 256, row = idx >> 5, c4 = (idx & 31) << 2;
            *reinterpret_cast<float4*>(w_s + row * 128 + c4) = pw[j];
        }
        __syncthreads();
        if (kt + 32 < 256) {
            pa = *reinterpret_cast<const float4*>(ap + kt + 32);
            #pragma unroll
            for (int j = 0; j < 4; j++) {
                int idx = tid + j * 256, row = idx >> 5, c4 = (idx & 31) << 2;
                pw[j] = *reinterpret_cast<const float4*>(wrow + (size_t)(kt + 32 + row) * ZN + n0 + c4);
            }
        }
        #pragma unroll
        for (int k = 0; k < 32; k++) {
            float4 a = *reinterpret_cast<const float4*>(a_s + k * 36 + (bq << 2));
            ulonglong2 w = *reinterpret_cast<const ulonglong2*>(w_s + k * 128 + (tx << 2));
            ull ax = pack2(a.x, a.x), ay = pack2(a.y, a.y);
            ull az = pack2(a.z, a.z), aw = pack2(a.w, a.w);
            acc[0][0] = fma2(ax, w.x, acc[0][0]); acc[0][1] = fma2(ax, w.y, acc[0][1]);
            acc[1][0] = fma2(ay, w.x, acc[1][0]); acc[1][1] = fma2(ay, w.y, acc[1][1]);
            acc[2][0] = fma2(az, w.x, acc[2][0]); acc[2][1] = fma2(az, w.y, acc[2][1]);
            acc[3][0] = fma2(aw, w.x, acc[3][0]); acc[3][1] = fma2(aw, w.y, acc[3][1]);
        }
        __syncthreads();
    }

    #pragma unroll
    for (int i = 0; i < 4; i++) {
        float2 r0 = unpack2(acc[i][0]);
        float2 r1 = unpack2(acc[i][1]);
        float4 o; o.x = r0.x; o.y = r0.y; o.z = r1.x; o.w = r1.y;
        *reinterpret_cast<float4*>(pout + (size_t)((bq << 2) + i) * ZN + n0 + (tx << 2)) = o;
    }
}

__device__ __forceinline__ float sigf(float x) { return 1.f / (1.f + expf(-x)); }

__device__ __forceinline__ void gates1_work(int t, int start, int stride) {
    for (int idx = start; idx < BB * HH; idx += stride) {
        int b = idx >> 10, n = idx & (HH - 1);
        const float* zx = g_zx + ((size_t)t * BB + b) * ZN;
        float zi = zx[n], zj = zx[HH + n], zf = zx[2 * HH + n], zo = zx[3 * HH + n];
        #pragma unroll
        for (int kc = 0; kc < 4; kc++) {
            const float* p = g_z1p + ((size_t)kc * BB + b) * ZN;
            zi += p[n]; zj += p[HH + n]; zf += p[2 * HH + n]; zo += p[3 * HH + n];
        }
        float cn = g_c1[idx] * sigf(zf) + sigf(zi) * tanhf(zj);
        g_c1[idx] = cn;
        g_h1[idx] = tanhf(cn) * sigf(zo);
    }
}

__device__ __forceinline__ void gates2_work(int t, const float* __restrict__ b2,
                                            int start, int stride) {
    for (int idx = start; idx < BB * HH; idx += stride) {
        int b = idx >> 10, n = idx & (HH - 1);
        float zi = b2[n], zj = b2[HH + n], zf = b2[2 * HH + n], zo = b2[3 * HH + n];
        #pragma unroll
        for (int kc = 0; kc < 8; kc++) {
            const float* p = g_z2p + ((size_t)kc * BB + b) * ZN;
            zi += p[n]; zj += p[HH + n]; zf += p[2 * HH + n]; zo += p[3 * HH + n];
        }
        float cn = g_c2[idx] * sigf(zf) + sigf(zi) * tanhf(zj);
        g_c2[idx] = cn;
        float hn = tanhf(cn) * sigf(zo);
        g_h2[idx] = hn;
        g_hs[((size_t)b * TT + t) * HH + n] = hn;
    }
}

__global__ void __launch_bounds__(256) lstm_kernel(const float* __restrict__ W1,
                                                   const float* __restrict__ W2,
                                                   const float* __restrict__ b2) {
    __shared__ __align__(16) float a_s[32 * 36];
    __shared__ __align__(16) float w_s[32 * 128];
    unsigned int bar = 0;
    const int bid = blockIdx.x, tid = threadIdx.x;

    for (int i = bid * 256 + tid; i < BB * HH; i += NBLK * 256) {
        g_h1[i] = 0.f; g_c1[i] = 0.f; g_h2[i] = 0.f; g_c2[i] = 0.f;
    }
    grid_bar(++bar);

    for (int t = 0; t < TT; t++) {
        // Phase A: gates2(t-1) on spare blocks || layer1 GEMM(t) on blocks 0..127
        if (bid < 128) {
            int ntile = bid & 31, kc = bid >> 5;
            gemm_task(g_h1 + kc * 256,
                      W1 + (size_t)(EE + kc * 256) * ZN,
                      g_z1p + (size_t)kc * BB * ZN,
                      ntile * 128, a_s, w_s);
        } else if (t > 0) {
            gates2_work(t - 1, b2, (bid - 128) * 256 + tid, 20 * 256);
        }
        grid_bar(++bar);

        // Phase B: gates1(t) on spare blocks || layer2 GEMM h2-half (kc 4..7, uses h2(t-1))
        if (bid < 128) {
            int ntile = bid & 31, kc = 4 + (bid >> 5);
            gemm_task(g_h2 + (kc - 4) * 256,
                      W2 + (size_t)kc * 256 * ZN,
                      g_z2p + (size_t)kc * BB * ZN,
                      ntile * 128, a_s, w_s);
        } else {
            gates1_work(t, (bid - 128) * 256 + tid, 20 * 256);
        }
        grid_bar(++bar);

        // Phase C: layer2 GEMM h1-half (kc 0..3, uses h1(t))
        if (bid < 128) {
            int ntile = bid & 31, kc = bid >> 5;
            gemm_task(g_h1 + kc * 256,
                      W2 + (size_t)kc * 256 * ZN,
                      g_z2p + (size_t)kc * BB * ZN,
                      ntile * 128, a_s, w_s);
        }
        grid_bar(++bar);
    }
    gates2_work(TT - 1, b2, bid * 256 + tid, NBLK * 256);
}

// ============================================================================
// bf16 hi/lo split conversion
// ============================================================================
__device__ __forceinline__ void split4(float4 v, uint2& hi, uint2& lo) {
    __nv_bfloat16 h0 = __float2bfloat16_rn(v.x);
    __nv_bfloat16 h1 = __float2bfloat16_rn(v.y);
    __nv_bfloat16 h2 = __float2bfloat16_rn(v.z);
    __nv_bfloat16 h3 = __float2bfloat16_rn(v.w);
    __nv_bfloat16 l0 = __float2bfloat16_rn(v.x - __bfloat162float(h0));
    __nv_bfloat16 l1 = __float2bfloat16_rn(v.y - __bfloat162float(h1));
    __nv_bfloat16 l2 = __float2bfloat16_rn(v.z - __bfloat162float(h2));
    __nv_bfloat16 l3 = __float2bfloat16_rn(v.w - __bfloat162float(h3));
    __nv_bfloat162 hp0 = {h0, h1}, hp1 = {h2, h3}, lp0 = {l0, l1}, lp1 = {l2, l3};
    hi.x = *reinterpret_cast<uint32_t*>(&hp0);
    hi.y = *reinterpret_cast<uint32_t*>(&hp1);
    lo.x = *reinterpret_cast<uint32_t*>(&lp0);
    lo.y = *reinterpret_cast<uint32_t*>(&lp1);
}

__global__ void __launch_bounds__(256) conv_hs_kernel() {
    size_t i = (size_t)blockIdx.x * 256 + threadIdx.x;
    float4 v = reinterpret_cast<const float4*>(g_hs)[i];
    uint2 hi, lo;
    split4(v, hi, lo);
    reinterpret_cast<uint2*>(g_Ahi)[i] = hi;
    reinterpret_cast<uint2*>(g_Alo)[i] = lo;
}

__global__ void __launch_bounds__(256) conv_w_kernel(const float* __restrict__ Wv) {
    size_t i = (size_t)blockIdx.x * 256 + threadIdx.x;
    float4 v = reinterpret_cast<const float4*>(Wv)[i];
    uint2 hi, lo;
    split4(v, hi, lo);
    reinterpret_cast<uint2*>(g_Whi)[i] = hi;
    reinterpret_cast<uint2*>(g_Wlo)[i] = lo;
}

// ============================================================================
// HMMA logits GEMM: out[4096][32000] = hs @ Wv^T + sb  (bf16x3 split)
// BM=128, BN=128, K-chunk 64 (128B SW128 rows), cp.async double buffer.
// 8 warps: warp (wm, wn) = (wid&3, wid>>2) owns 32(M) x 64(N).
// ============================================================================
#define LSTAGE 65536                 // Ahi 16K | Alo 16K | Whi 16K | Wlo 16K
#define LSMEM_TOTAL (2 * LSTAGE)     // 131072

__global__ void __launch_bounds__(256) logits_hmma_kernel(const float* __restrict__ sbias,
                                                          float* __restrict__ out) {
    extern __shared__ __align__(1024) char smem[];
    const uint32_t sb32 = smem_u32(smem);
    const int tid  = threadIdx.x;
    const int wid  = tid >> 5, lane = tid & 31;
    const int m0   = blockIdx.x * 128;
    const int v0   = blockIdx.y * 128;
    const int wm   = wid & 3;
    const int wn   = wid >> 2;

    // staging indices: each thread copies 16B pieces; 32 rows per round
    const int r8  = tid >> 3;          // 0..31
    const int l16 = (tid & 7) * 16;    // byte offset within 128B row

    const char* pAhi = reinterpret_cast<const char*>(g_Ahi);
    const char* pAlo = reinterpret_cast<const char*>(g_Alo);
    const char* pWhi = reinterpret_cast<const char*>(g_Whi);
    const char* pWlo = reinterpret_cast<const char*>(g_Wlo);

    auto stage = [&](int c) {
        const uint32_t sb = sb32 + (c & 1) * LSTAGE;
        #pragma unroll
        for (int rr = 0; rr < 4; rr++) {
            int row = rr * 32 + r8;
            size_t goffA = (size_t)(m0 + row) * (HH * 2) + c * 128 + l16;
            size_t goffW = (size_t)(v0 + row) * (HH * 2) + c * 128 + l16;
            uint32_t soff = SWZ128((uint32_t)(row * 128 + l16));
            CP_ASYNC16(sb + soff,         pAhi + goffA);
            CP_ASYNC16(sb + 16384 + soff, pAlo + goffA);
            CP_ASYNC16(sb + 32768 + soff, pWhi + goffW);
            CP_ASYNC16(sb + 49152 + soff, pWlo + goffW);
        }
        CP_COMMIT();
    };

    float acc[2][8][4];
    #pragma unroll
    for (int mt = 0; mt < 2; mt++)
        #pragma unroll
        for (int nt = 0; nt < 8; nt++)
            #pragma unroll
            for (int j = 0; j < 4; j++) acc[mt][nt][j] = 0.f;

    stage(0);

    // ldmatrix lane address components (row/kb within tile), computed once
    const int a_row = wm * 32 + (lane & 15);          // + mt*16
    const int a_kbs = ((lane >> 4) & 1) * 16;         // + ks*32
    const int b_row = wn * 64 + ((lane >> 4) & 1) * 8 + (lane & 7);   // + p*16
    const int b_kbs = ((lane >> 3) & 1) * 16;         // + ks*32

    for (int c = 0; c < 16; c++) {
        CP_WAIT0();
        __syncthreads();
        if (c < 15) stage(c + 1);

        const uint32_t sb = sb32 + (c & 1) * LSTAGE;
        #pragma unroll
        for (int ks = 0; ks < 4; ks++) {
            uint32_t ahi[2][4], alo[2][4];
            #pragma unroll
            for (int mt = 0; mt < 2; mt++) {
                uint32_t off = SWZ128((uint32_t)((a_row + mt * 16) * 128 + ks * 32 + a_kbs));
                LDSM_X4(ahi[mt][0], ahi[mt][1], ahi[mt][2], ahi[mt][3], sb + off);
                LDSM_X4(alo[mt][0], alo[mt][1], alo[mt][2], alo[mt][3], sb + 16384 + off);
            }
            uint32_t bhi[8][2], blo[8][2];
            #pragma unroll
            for (int p = 0; p < 4; p++) {
                uint32_t off = SWZ128((uint32_t)((b_row + p * 16) * 128 + ks * 32 + b_kbs));
                LDSM_X4(bhi[2 * p][0], bhi[2 * p][1], bhi[2 * p + 1][0], bhi[2 * p + 1][1],
                        sb + 32768 + off);
                LDSM_X4(blo[2 * p][0], blo[2 * p][1], blo[2 * p + 1][0], blo[2 * p + 1][1],
                        sb + 49152 + off);
            }
            #pragma unroll
            for (int mt = 0; mt < 2; mt++)
                #pragma unroll
                for (int nt = 0; nt < 8; nt++) {
                    MMA16816(acc[mt][nt], ahi[mt], bhi[nt]);
                    MMA16816(acc[mt][nt], ahi[mt], blo[nt]);
                    MMA16816(acc[mt][nt], alo[mt], bhi[nt]);
                }
        }
        __syncthreads();
    }

    // epilogue
    #pragma unroll
    for (int mt = 0; mt < 2; mt++) {
        int row = m0 + wm * 32 + mt * 16 + (lane >> 2);
        #pragma unroll
        for (int nt = 0; nt < 8; nt++) {
            int col = v0 + wn * 64 + nt * 8 + (lane & 3) * 2;
            float2 bv = *reinterpret_cast<const float2*>(sbias + col);
            float2 o0, o1;
            o0.x = acc[mt][nt][0] + bv.x; o0.y = acc[mt][nt][1] + bv.y;
            o1.x = acc[mt][nt][2] + bv.x; o1.y = acc[mt][nt][3] + bv.y;
            *reinterpret_cast<float2*>(out + (size_t)row * VV + col)       = o0;
            *reinterpret_cast<float2*>(out + (size_t)(row + 8) * VV + col) = o1;
        }
    }
}

// ---------------- launch ----------------
extern "C" void kernel_launch(void* const* d_in, const int* in_sizes, int n_in,
                              void* d_out, int out_size) {
    const int*   ids = (const int*)d_in[0];     // [B,T] int32
    const float* emb = (const float*)d_in[1];   // [VOCAB,E]
    const float* W1  = (const float*)d_in[2];   // [E+H, 4H]
    const float* b1  = (const float*)d_in[3];   // [4H]
    const float* W2  = (const float*)d_in[4];   // [2H, 4H]
    const float* b2  = (const float*)d_in[5];   // [4H]
    const float* Wv  = (const float*)d_in[6];   // [VOCAB, H]
    const float* sb  = (const float*)d_in[7];   // [VOCAB]
    float* out = (float*)d_out;                 // [B*T, VOCAB]

    cudaFuncSetAttribute(logits_hmma_kernel,
                         cudaFuncAttributeMaxDynamicSharedMemorySize, LSMEM_TOTAL);

    dim3 zxg(ZN / 64, (TT * BB) / 64);
    zx_kernel<<<zxg, 256>>>(ids, emb, W1, b1);

    conv_w_kernel<<<(VV * HH / 4) / 256, 256>>>(Wv);   // independent of lstm

    lstm_kernel<<<NBLK, 256>>>(W1, W2, b2);

    conv_hs_kernel<<<(BB * TT * HH / 4) / 256, 256>>>();

    dim3 lg((BB * TT) / 128, VV / 128);   // x = M tiles (32), y = N tiles (250)
    logits_hmma_kernel<<<lg, 256, LSMEM_TOTAL>>>(sb, out);
}